// round 2
// baseline (speedup 1.0000x reference)
#include <cuda_runtime.h>

// SeqSelfAttention (Bahdanau additive, windowed) — GB300 sm_103a
// B=4, L=1024, D=128, U=32, WIDTH=64, EPS=1e-7
//
// Algebra: window-max softmax shift changes the result only through the +1e-7
// denominator by exp(Mw-Mfull) (rel err <~1e-6); ba cancels exactly.
// R2: warp-per-query restructure — softmax + AV entirely in registers,
// single __syncthreads per block, 8 warps/block.

#define LSEQ 1024
#define BB   4
#define DD   128
#define UU   32
#define TI   8
#define CW   72   // TI + 64 : union of windows for TI consecutive queries
#define NROWS (BB*LSEQ)

// scratch (allocation-free rule -> __device__ globals)
__device__ float g_q [NROWS*UU];
__device__ float g_kb[NROWS*UU];

__device__ __forceinline__ float fast_tanh(float x){
    float y;
    asm("tanh.approx.f32 %0, %1;" : "=f"(y) : "f"(x));
    return y;
}

// ---------------------------------------------------------------------------
// Kernel 1: q = x @ Wt ; kb = x @ Wx + bh      (x:[4096,128], W:[128,32])
// 256 blocks x 256 threads, 16 rows per block (warp -> 2 rows).
// ---------------------------------------------------------------------------
#define QK_ROWS 16
__global__ __launch_bounds__(256) void qk_kernel(
        const float* __restrict__ x,
        const float* __restrict__ Wt,
        const float* __restrict__ Wx,
        const float* __restrict__ bh)
{
    __shared__ float xs [QK_ROWS*128];  // 8 KB
    __shared__ float wts[128*32];       // 16 KB
    __shared__ float wxs[128*32];       // 16 KB
    const int t    = threadIdx.x;
    const int row0 = blockIdx.x * QK_ROWS;

    {   // stage tiles (fully coalesced float4 copies)
        const float4* xg = (const float4*)(x + row0*DD);
        float4* xs4 = (float4*)xs;
        #pragma unroll
        for (int i = t; i < QK_ROWS*32; i += 256) xs4[i] = xg[i];
        const float4* wtg = (const float4*)Wt; float4* wt4 = (float4*)wts;
        const float4* wxg = (const float4*)Wx; float4* wx4 = (float4*)wxs;
        #pragma unroll
        for (int i = t; i < 1024; i += 256){ wt4[i] = wtg[i]; wx4[i] = wxg[i]; }
    }
    __syncthreads();

    const int u  = t & 31;        // lane = unit  -> conflict-free W reads
    const int rg = t >> 5;        // warp id -> 2 rows, broadcast x reads
    float aq0=0,aq1=0, ak0=0,ak1=0;
    const float* xr = xs + rg*2*DD;
    #pragma unroll 8
    for (int d = 0; d < DD; d++){
        const float wt = wts[d*32+u];
        const float wx = wxs[d*32+u];
        const float x0 = xr[d], x1 = xr[DD+d];
        aq0 += x0*wt; aq1 += x1*wt;
        ak0 += x0*wx; ak1 += x1*wx;
    }
    const float bhv = bh[u];
    const int r = row0 + rg*2;
    g_q [(r+0)*UU+u] = aq0;      g_q [(r+1)*UU+u] = aq1;
    g_kb[(r+0)*UU+u] = ak0+bhv;  g_kb[(r+1)*UU+u] = ak1+bhv;
}

// ---------------------------------------------------------------------------
// Kernel 2: windowed additive attention. grid (L/TI, B), 256 threads.
// Warp w owns query i0+w. One __syncthreads total; softmax + AV in registers.
// smem: xs[72][128] | kbs[72][33] | qs[8][32] | was[32]
// ---------------------------------------------------------------------------
#define OFF_XS   0
#define OFF_KBS  (CW*DD)                 // 9216
#define OFF_QS   (OFF_KBS + CW*33)       // 11592
#define OFF_WAS  (OFF_QS + TI*UU)        // 11848
#define SMEM_FLOATS (OFF_WAS + UU)       // 11880 floats = 47520 B

extern __shared__ float smem[];

__global__ __launch_bounds__(256) void attn_kernel(
        const float* __restrict__ x,
        const float* __restrict__ Wa,
        float* __restrict__ out)
{
    float* xs   = smem + OFF_XS;
    float* kbs  = smem + OFF_KBS;
    float* qs   = smem + OFF_QS;
    float* was  = smem + OFF_WAS;

    const int t    = threadIdx.x;
    const int i0   = blockIdx.x * TI;
    const int base = blockIdx.y * LSEQ;   // row base for this batch

    // ---- stage x window [72][128] (float4) + kb window [72][33] ----
    {
        float4* xs4 = (float4*)xs;
        const float4* xg4 = (const float4*)x;
        #pragma unroll
        for (int i = 0; i < 9; i++){
            const int idx = t + i*256;            // float4 idx into [72][32]
            const int c = idx >> 5, dq = idx & 31;
            const int j = i0 - 32 + c;
            float4 v = make_float4(0.f,0.f,0.f,0.f);
            if (j >= 0 && j < LSEQ) v = xg4[(base + j)*32 + dq];
            xs4[c*32 + dq] = v;
        }
        #pragma unroll
        for (int i = 0; i < 9; i++){
            const int idx = t + i*256;
            const int c = idx >> 5, u = idx & 31;
            const int j = i0 - 32 + c;
            kbs[c*33 + u] = (j >= 0 && j < LSEQ) ? g_kb[(base + j)*UU + u] : 0.f;
        }
        qs[t & 255] = g_q[(base + i0)*UU + t];    // 8 rows x 32 u = 256
        if (t < 32) was[t] = Wa[t];
    }
    __syncthreads();

    const int w = t >> 5;                 // warp = query index within tile
    const int l = t & 31;
    const int c0 = w + l, c1 = c0 + 32;   // this lane's two window keys

    // ---- logits: e = sum_u Wa_u * tanh(q_u + kb_u) ----
    float e0 = 0.f, e1 = 0.f;
    {
        const float* qrow = qs + w*UU;
        const float* kp0  = kbs + c0*33;
        const float* kp1  = kbs + c1*33;
        #pragma unroll
        for (int u = 0; u < UU; u++){
            const float qv  = qrow[u];    // LDS broadcast
            const float wav = was[u];     // LDS broadcast
            e0 += wav * fast_tanh(qv + kp0[u]);
            e1 += wav * fast_tanh(qv + kp1[u]);
        }
        const int j0 = i0 - 32 + c0;
        if (j0 < 0 || j0 >= LSEQ)          e0 = -1e30f;
        if (j0 + 32 < 0 || j0+32 >= LSEQ)  e1 = -1e30f;
    }

    // ---- warp softmax over the 64-key window (registers only) ----
    float a0, a1;
    {
        float m = fmaxf(e0, e1);
        #pragma unroll
        for (int o = 16; o; o >>= 1) m = fmaxf(m, __shfl_xor_sync(0xffffffffu, m, o));
        const float w0 = __expf(e0 - m);   // -1e30 keys -> 0
        const float w1 = __expf(e1 - m);
        float s = w0 + w1;
        #pragma unroll
        for (int o = 16; o; o >>= 1) s += __shfl_xor_sync(0xffffffffu, s, o);
        const float inv = 1.f / (s + 1e-7f);
        a0 = w0 * inv; a1 = w1 * inv;
    }

    // ---- v[w][:] = sum_c a_c * x[c][:], lane l = float4 column l ----
    {
        const float4* xs4 = (const float4*)xs;
        float4 acc = make_float4(0.f,0.f,0.f,0.f);
        #pragma unroll 8
        for (int k = 0; k < 32; k++){
            const float av = __shfl_sync(0xffffffffu, a0, k);
            const float4 xv = xs4[(w + k)*32 + l];
            acc.x += av*xv.x; acc.y += av*xv.y; acc.z += av*xv.z; acc.w += av*xv.w;
        }
        #pragma unroll 8
        for (int k = 0; k < 32; k++){
            const float av = __shfl_sync(0xffffffffu, a1, k);
            const float4 xv = xs4[(w + 32 + k)*32 + l];
            acc.x += av*xv.x; acc.y += av*xv.y; acc.z += av*xv.z; acc.w += av*xv.w;
        }
        float4* out4 = (float4*)out;
        out4[(base + i0 + w)*32 + l] = acc;
    }
}

// ---------------------------------------------------------------------------
extern "C" void kernel_launch(void* const* d_in, const int* in_sizes, int n_in,
                              void* d_out, int out_size)
{
    const float* x  = (const float*)d_in[0];
    const float* Wt = (const float*)d_in[1];
    const float* Wx = (const float*)d_in[2];
    const float* bh = (const float*)d_in[3];
    const float* Wa = (const float*)d_in[4];
    // d_in[5] = ba : cancels exactly in the shifted softmax -> unused
    float* out = (float*)d_out;

    qk_kernel<<<NROWS/QK_ROWS, 256>>>(x, Wt, Wx, bh);

    cudaFuncSetAttribute(attn_kernel,
                         cudaFuncAttributeMaxDynamicSharedMemorySize,
                         SMEM_FLOATS*4 + 256);
    dim3 grid(LSEQ/TI, BB);
    attn_kernel<<<grid, 256, SMEM_FLOATS*4>>>(x, Wa, out);
}

// round 3
// speedup vs baseline: 1.2576x; 1.2576x over previous
#include <cuda_runtime.h>

// SeqSelfAttention (Bahdanau additive, windowed) — GB300 sm_103a
// B=4, L=1024, D=128, U=32, WIDTH=64, EPS=1e-7
//
// Algebra: window-max softmax shift changes the result only through the +1e-7
// denominator by exp(Mw-Mfull) (rel err <~1e-6); ba cancels exactly.
// R3: 2 queries/warp (shared xv reads), float2 kb loads, smem-broadcast
// attention weights (no SHFL in AV), register-tiled qk (4 rows/warp).

#define LSEQ 1024
#define BB   4
#define DD   128
#define UU   32
#define TI   8
#define CW   72   // TI + 64 : union of windows for TI consecutive queries
#define NROWS (BB*LSEQ)

__device__ float g_q [NROWS*UU];
__device__ float g_kb[NROWS*UU];

__device__ __forceinline__ float fast_tanh(float x){
    float y;
    asm("tanh.approx.f32 %0, %1;" : "=f"(y) : "f"(x));
    return y;
}

// ---------------------------------------------------------------------------
// Kernel 1: q = x @ Wt ; kb = x @ Wx + bh      (x:[4096,128], W:[128,32])
// 256 blocks x 128 threads; warp owns 4 rows, lane owns unit u.
// ---------------------------------------------------------------------------
#define QK_RPB 16
__global__ __launch_bounds__(128) void qk_kernel(
        const float* __restrict__ x,
        const float* __restrict__ Wt,
        const float* __restrict__ Wx,
        const float* __restrict__ bh)
{
    __shared__ float xs [QK_RPB*128];   // 8 KB
    __shared__ float wts[128*32];       // 16 KB
    __shared__ float wxs[128*32];       // 16 KB
    const int t    = threadIdx.x;
    const int row0 = blockIdx.x * QK_RPB;

    {   // stage (coalesced float4)
        const float4* xg = (const float4*)(x + row0*DD);
        float4* xs4 = (float4*)xs;
        #pragma unroll
        for (int i = 0; i < 4; i++) xs4[t + i*128] = xg[t + i*128];
        const float4* wtg = (const float4*)Wt; float4* wt4 = (float4*)wts;
        const float4* wxg = (const float4*)Wx; float4* wx4 = (float4*)wxs;
        #pragma unroll
        for (int i = 0; i < 8; i++){
            wt4[t + i*128] = wtg[t + i*128];
            wx4[t + i*128] = wxg[t + i*128];
        }
    }
    __syncthreads();

    const int u  = t & 31;
    const int rg = t >> 5;          // warp -> 4 rows
    const int rb = rg * 4;
    float aq0=0,aq1=0,aq2=0,aq3=0, ak0=0,ak1=0,ak2=0,ak3=0;
    const float4* xs4 = (const float4*)xs;

    #pragma unroll 8
    for (int d4 = 0; d4 < 32; d4++){
        const int db = d4*4*32 + u;
        const float wt0 = wts[db], wt1 = wts[db+32], wt2 = wts[db+64], wt3 = wts[db+96];
        const float wx0 = wxs[db], wx1 = wxs[db+32], wx2 = wxs[db+64], wx3 = wxs[db+96];
        const float4 x0 = xs4[(rb+0)*32 + d4];   // broadcast
        const float4 x1 = xs4[(rb+1)*32 + d4];
        const float4 x2 = xs4[(rb+2)*32 + d4];
        const float4 x3 = xs4[(rb+3)*32 + d4];
        aq0 += x0.x*wt0 + x0.y*wt1 + x0.z*wt2 + x0.w*wt3;
        aq1 += x1.x*wt0 + x1.y*wt1 + x1.z*wt2 + x1.w*wt3;
        aq2 += x2.x*wt0 + x2.y*wt1 + x2.z*wt2 + x2.w*wt3;
        aq3 += x3.x*wt0 + x3.y*wt1 + x3.z*wt2 + x3.w*wt3;
        ak0 += x0.x*wx0 + x0.y*wx1 + x0.z*wx2 + x0.w*wx3;
        ak1 += x1.x*wx0 + x1.y*wx1 + x1.z*wx2 + x1.w*wx3;
        ak2 += x2.x*wx0 + x2.y*wx1 + x2.z*wx2 + x2.w*wx3;
        ak3 += x3.x*wx0 + x3.y*wx1 + x3.z*wx2 + x3.w*wx3;
    }
    const float bhv = bh[u];
    const int r = row0 + rb;
    g_q [(r+0)*UU+u] = aq0;      g_q [(r+1)*UU+u] = aq1;
    g_q [(r+2)*UU+u] = aq2;      g_q [(r+3)*UU+u] = aq3;
    g_kb[(r+0)*UU+u] = ak0+bhv;  g_kb[(r+1)*UU+u] = ak1+bhv;
    g_kb[(r+2)*UU+u] = ak2+bhv;  g_kb[(r+3)*UU+u] = ak3+bhv;
}

// ---------------------------------------------------------------------------
// Kernel 2: windowed attention. grid (L/TI, B), 128 threads (4 warps).
// Warp w owns queries 2w, 2w+1. Lane l -> keys 2w+l, 2w+32+l (q0) and
// 2w+1+l, 2w+33+l (q1). xv reads shared across both queries in AV.
// smem: xs[72][128] | kbs[72][34] | qs[8][32] | was[32] | Aw[4][66 float2]
// ---------------------------------------------------------------------------
#define KBS  34
#define OFF_XS   0
#define OFF_KBS  (CW*DD)                   // 9216
#define OFF_QS   (OFF_KBS + CW*KBS)        // 11664
#define OFF_WAS  (OFF_QS + TI*UU)          // 11920
#define OFF_AW   (OFF_WAS + UU)            // 11952
#define SMEM_FLOATS (OFF_AW + 4*66*2)      // 12480 floats = 49920 B

extern __shared__ float smem[];

__global__ __launch_bounds__(128) void attn_kernel(
        const float* __restrict__ x,
        const float* __restrict__ Wa,
        float* __restrict__ out)
{
    float* xs   = smem + OFF_XS;
    float* kbs  = smem + OFF_KBS;
    float* qs   = smem + OFF_QS;
    float* was  = smem + OFF_WAS;
    float* Aw   = smem + OFF_AW;

    const int t    = threadIdx.x;
    const int i0   = blockIdx.x * TI;
    const int base = blockIdx.y * LSEQ;

    // ---- stage: xs[72][128] float4, kbs[72][34] float2, qs, was ----
    {
        float4* xs4 = (float4*)xs;
        const float4* xg4 = (const float4*)x;
        #pragma unroll
        for (int i = 0; i < 18; i++){
            const int idx = t + i*128;            // [0,2304) float4 of [72][32]
            const int c = idx >> 5, dq = idx & 31;
            const int j = i0 - 32 + c;
            float4 v = make_float4(0.f,0.f,0.f,0.f);
            if (j >= 0 && j < LSEQ) v = xg4[(base + j)*32 + dq];
            xs4[c*32 + dq] = v;
        }
        #pragma unroll
        for (int i = 0; i < 9; i++){
            const int idx = t + i*128;            // [0,1152) float2 of [72][16]
            const int c = idx >> 4, u2 = idx & 15;
            const int j = i0 - 32 + c;
            float2 v = make_float2(0.f, 0.f);
            if (j >= 0 && j < LSEQ)
                v = ((const float2*)(g_kb + (base + j)*UU))[u2];
            *(float2*)(kbs + c*KBS + 2*u2) = v;
        }
        ((float2*)qs)[t] = ((const float2*)(g_q + (base + i0)*UU))[t];
        if (t < 32) was[t] = Wa[t];
    }
    __syncthreads();

    const int w = t >> 5;
    const int l = t & 31;
    const int rA = 2*w + l;          // q0 key rows: rA, rA+32
    // q1 key rows: rA+1, rA+33

    // ---- logits: 4 independent tanh series (float2 kb, broadcast q/wa) ----
    float e00 = 0.f, e01 = 0.f, e10 = 0.f, e11 = 0.f;
    {
        const float* q0p = qs + 2*w*UU;
        const float* q1p = q0p + UU;
        const float* kAp = kbs + rA*KBS;
        #pragma unroll
        for (int u2 = 0; u2 < 16; u2++){
            const float2 wa2 = *(const float2*)(was + 2*u2);
            const float2 q0v = *(const float2*)(q0p + 2*u2);
            const float2 q1v = *(const float2*)(q1p + 2*u2);
            const float2 kA  = *(const float2*)(kAp + 2*u2);
            const float2 kB  = *(const float2*)(kAp + 32*KBS + 2*u2);
            const float2 kC  = *(const float2*)(kAp + KBS + 2*u2);
            const float2 kD  = *(const float2*)(kAp + 33*KBS + 2*u2);
            e00 += wa2.x*fast_tanh(q0v.x + kA.x) + wa2.y*fast_tanh(q0v.y + kA.y);
            e01 += wa2.x*fast_tanh(q0v.x + kB.x) + wa2.y*fast_tanh(q0v.y + kB.y);
            e10 += wa2.x*fast_tanh(q1v.x + kC.x) + wa2.y*fast_tanh(q1v.y + kC.y);
            e11 += wa2.x*fast_tanh(q1v.x + kD.x) + wa2.y*fast_tanh(q1v.y + kD.y);
        }
    }
    // sequence-boundary masks (all keys in-window by construction)
    {
        const int j0 = i0 - 32 + rA;         // key of e00
        if (j0 < 0 || j0 >= LSEQ)           e00 = -1e30f;
        if (j0 + 32 >= LSEQ)                e01 = -1e30f;
        if (j0 + 1 < 0 || j0 + 1 >= LSEQ)   e10 = -1e30f;
        if (j0 + 33 >= LSEQ)                e11 = -1e30f;
    }

    // ---- two warp softmaxes (registers only) ----
    float a00, a01, a10, a11;
    {
        float m0 = fmaxf(e00, e01), m1 = fmaxf(e10, e11);
        #pragma unroll
        for (int o = 16; o; o >>= 1){
            m0 = fmaxf(m0, __shfl_xor_sync(0xffffffffu, m0, o));
            m1 = fmaxf(m1, __shfl_xor_sync(0xffffffffu, m1, o));
        }
        const float w00 = __expf(e00 - m0), w01 = __expf(e01 - m0);
        const float w10 = __expf(e10 - m1), w11 = __expf(e11 - m1);
        float s0 = w00 + w01, s1 = w10 + w11;
        #pragma unroll
        for (int o = 16; o; o >>= 1){
            s0 += __shfl_xor_sync(0xffffffffu, s0, o);
            s1 += __shfl_xor_sync(0xffffffffu, s1, o);
        }
        const float inv0 = 1.f / (s0 + 1e-7f);
        const float inv1 = 1.f / (s1 + 1e-7f);
        a00 = w00*inv0; a01 = w01*inv0; a10 = w10*inv1; a11 = w11*inv1;
    }

    // ---- publish weights: slot k <-> key c = 2w+k; (.x = q0, .y = q1) ----
    float* A = Aw + w*132;                   // 66 float2 slots
    A[2*l]          = a00;                   // slot l      .x
    A[2*(l+1) + 1]  = a10;                   // slot l+1    .y
    A[2*(l+32)]     = a01;                   // slot l+32   .x
    A[2*(l+33) + 1] = a11;                   // slot l+33   .y
    if (l == 0){ A[2*64] = 0.f; A[1] = 0.f; }  // q0@slot64, q1@slot0
    __syncwarp();

    // ---- AV: shared xv read feeds both queries ----
    {
        const float4* xs4 = (const float4*)xs;
        const float2* A2  = (const float2*)A;
        float4 acc0 = make_float4(0.f,0.f,0.f,0.f);
        float4 acc1 = make_float4(0.f,0.f,0.f,0.f);
        #pragma unroll 13
        for (int k = 0; k <= 64; k++){
            const float2 ab = A2[k];                 // broadcast LDS.64
            const float4 xv = xs4[(2*w + k)*32 + l]; // conflict-free LDS.128
            acc0.x += ab.x*xv.x; acc0.y += ab.x*xv.y;
            acc0.z += ab.x*xv.z; acc0.w += ab.x*xv.w;
            acc1.x += ab.y*xv.x; acc1.y += ab.y*xv.y;
            acc1.z += ab.y*xv.z; acc1.w += ab.y*xv.w;
        }
        float4* out4 = (float4*)out;
        out4[(base + i0 + 2*w    )*32 + l] = acc0;
        out4[(base + i0 + 2*w + 1)*32 + l] = acc1;
    }
}

// ---------------------------------------------------------------------------
extern "C" void kernel_launch(void* const* d_in, const int* in_sizes, int n_in,
                              void* d_out, int out_size)
{
    const float* x  = (const float*)d_in[0];
    const float* Wt = (const float*)d_in[1];
    const float* Wx = (const float*)d_in[2];
    const float* bh = (const float*)d_in[3];
    const float* Wa = (const float*)d_in[4];
    // d_in[5] = ba : cancels exactly in the shifted softmax -> unused
    float* out = (float*)d_out;

    qk_kernel<<<NROWS/QK_RPB, 128>>>(x, Wt, Wx, bh);

    cudaFuncSetAttribute(attn_kernel,
                         cudaFuncAttributeMaxDynamicSharedMemorySize,
                         SMEM_FLOATS*4 + 256);
    dim3 grid(LSEQ/TI, BB);
    attn_kernel<<<grid, 128, SMEM_FLOATS*4>>>(x, Wa, out);
}